// round 2
// baseline (speedup 1.0000x reference)
#include <cuda_runtime.h>
#include <cuda_bf16.h>

#define BB 32
#define TT 4096
#define HH 256
#define CHUNKS 32                        // blocks per batch row
#define ROWS_PER_BLOCK (TT / CHUNKS)     // 128
#define NTHREADS 256
#define NWARPS (NTHREADS / 32)           // 8
#define ROWS_PER_WARP (ROWS_PER_BLOCK / NWARPS) // 16

#define ALPHA 0.1f
#define ONE_MINUS_ALPHA 0.9f
#define LOG2_09 (-0.15200309344504997f)  // log2(0.9)
#define MASK_PENALTY 1000000.0f

__device__ float g_partial[BB * CHUNKS];

__global__ __launch_bounds__(NTHREADS)
void pool_stage1(const float* __restrict__ x,
                 const int*   __restrict__ mask,
                 const float* __restrict__ weight_ema,
                 const float* __restrict__ weight_mean,
                 const float* __restrict__ W)
{
    const int b     = blockIdx.x / CHUNKS;
    const int chunk = blockIdx.x % CHUNKS;
    const int tid   = threadIdx.x;
    const int wid   = tid >> 5;
    const int lane  = tid & 31;

    __shared__ float s_wsum;
    __shared__ float s_warp_acc[NWARPS];

    // Per-lane W slices (each lane owns 8 of the 256 W values)
    const float4* W4 = reinterpret_cast<const float4*>(W);
    const float4 wa = __ldg(W4 + lane);        // W[lane*4 .. +3]
    const float4 wb = __ldg(W4 + 32 + lane);   // W[128 + lane*4 .. +3]

    // Block-wide Wsum (computed once, identically in every block -> deterministic)
    if (wid == 0) {
        float s = wa.x + wa.y + wa.z + wa.w + wb.x + wb.y + wb.z + wb.w;
        #pragma unroll
        for (int off = 16; off > 0; off >>= 1)
            s += __shfl_xor_sync(0xffffffffu, s, off);
        if (lane == 0) s_wsum = s;
    }
    __syncthreads();

    const float wsum = s_wsum;
    const float we   = __ldg(weight_ema);
    const float wm   = __ldg(weight_mean);
    const float wm_over_T = wm * (1.0f / (float)TT);

    const int t_base = chunk * ROWS_PER_BLOCK + wid * ROWS_PER_WARP;
    const float4* xbase = reinterpret_cast<const float4*>(x) +
                          (size_t)(b * TT + t_base) * (HH / 4);
    const int* mrow = mask + b * TT + t_base;

    float acc = 0.0f;

    #pragma unroll 4
    for (int i = 0; i < ROWS_PER_WARP; i++) {
        const float4* xr = xbase + (size_t)i * (HH / 4);
        float4 a = __ldg(xr + lane);
        float4 c2 = __ldg(xr + 32 + lane);

        float dot = a.x * wa.x;
        dot = fmaf(a.y, wa.y, dot);
        dot = fmaf(a.z, wa.z, dot);
        dot = fmaf(a.w, wa.w, dot);
        dot = fmaf(c2.x, wb.x, dot);
        dot = fmaf(c2.y, wb.y, dot);
        dot = fmaf(c2.z, wb.z, dot);
        dot = fmaf(c2.w, wb.w, dot);

        // full-warp butterfly reduce -> every lane holds row dot
        #pragma unroll
        for (int off = 16; off > 0; off >>= 1)
            dot += __shfl_xor_sync(0xffffffffu, dot, off);

        const int t = t_base + i;
        // EMA weight: alpha*(1-a)^(T-1-t) for t>0, (1-a)^(T-1) for t==0
        float e = (float)(TT - 1 - t);
        float wt = exp2f(e * LOG2_09);
        if (t > 0) wt *= ALPHA;
        float c = fmaf(we, wt, wm_over_T);

        float pen = (__ldg(mrow + i) != 0) ? 0.0f : MASK_PENALTY;
        acc = fmaf(c, dot - pen * wsum, acc);
    }

    // All lanes hold identical acc (dot was fully reduced); lane 0 reports.
    if (lane == 0) s_warp_acc[wid] = acc;
    __syncthreads();

    if (wid == 0) {
        float v = (lane < NWARPS) ? s_warp_acc[lane] : 0.0f;
        #pragma unroll
        for (int off = 4; off > 0; off >>= 1)
            v += __shfl_xor_sync(0xffffffffu, v, off);
        if (lane == 0) g_partial[blockIdx.x] = v;
    }
}

__global__ __launch_bounds__(BB * 32)
void pool_stage2(const float* __restrict__ bias, float* __restrict__ out)
{
    const int b    = threadIdx.x >> 5;   // warp id = batch index
    const int lane = threadIdx.x & 31;

    float v = g_partial[b * CHUNKS + lane];  // CHUNKS == 32
    #pragma unroll
    for (int off = 16; off > 0; off >>= 1)
        v += __shfl_xor_sync(0xffffffffu, v, off);

    if (lane == 0) out[b] = v + __ldg(bias);
}

extern "C" void kernel_launch(void* const* d_in, const int* in_sizes, int n_in,
                              void* d_out, int out_size)
{
    const float* x    = (const float*)d_in[0];
    const int*   mask = (const int*)d_in[1];
    const float* we   = (const float*)d_in[2];
    const float* wm   = (const float*)d_in[3];
    const float* W    = (const float*)d_in[4];
    const float* bias = (const float*)d_in[5];
    float* out = (float*)d_out;

    pool_stage1<<<BB * CHUNKS, NTHREADS>>>(x, mask, we, wm, W);
    pool_stage2<<<1, BB * 32>>>(bias, out);
}

// round 3
// speedup vs baseline: 1.0678x; 1.0678x over previous
#include <cuda_runtime.h>
#include <cuda_bf16.h>

#define BB 32
#define TT 4096
#define HH 256
#define CHUNKS 32                        // blocks per batch row
#define ROWS_PER_BLOCK (TT / CHUNKS)     // 128
#define NTHREADS 256
#define NWARPS (NTHREADS / 32)           // 8
#define ROWS_PER_WARP (ROWS_PER_BLOCK / NWARPS) // 16
#define GRID (BB * CHUNKS)               // 1024

#define ALPHA 0.1f
#define LOG2_09 (-0.15200309344504997f)  // log2(0.9)
#define MASK_PENALTY 1000000.0f

__device__ float g_partial[GRID];
__device__ unsigned int g_count = 0;

__global__ __launch_bounds__(NTHREADS)
void pool_fused(const float* __restrict__ x,
                const int*   __restrict__ mask,
                const float* __restrict__ weight_ema,
                const float* __restrict__ weight_mean,
                const float* __restrict__ W,
                const float* __restrict__ bias,
                float*       __restrict__ out)
{
    const int b     = blockIdx.x / CHUNKS;
    const int chunk = blockIdx.x % CHUNKS;
    const int tid   = threadIdx.x;
    const int wid   = tid >> 5;
    const int lane  = tid & 31;

    __shared__ float s_warp_acc[NWARPS];
    __shared__ bool  s_is_last;

    // Per-lane W slices (each lane owns 8 of the 256 W values)
    const float4* W4 = reinterpret_cast<const float4*>(W);
    const float4 wa = __ldg(W4 + lane);        // W[lane*4 .. +3]
    const float4 wb = __ldg(W4 + 32 + lane);   // W[128 + lane*4 .. +3]

    // Warp-wide Wsum (identical in every warp -> deterministic)
    float wsum = wa.x + wa.y + wa.z + wa.w + wb.x + wb.y + wb.z + wb.w;
    #pragma unroll
    for (int off = 16; off > 0; off >>= 1)
        wsum += __shfl_xor_sync(0xffffffffu, wsum, off);

    const float we        = __ldg(weight_ema);
    const float wm_over_T = __ldg(weight_mean) * (1.0f / (float)TT);

    const int t_base = chunk * ROWS_PER_BLOCK + wid * ROWS_PER_WARP;
    const float4* xbase = reinterpret_cast<const float4*>(x) +
                          (size_t)(b * TT + t_base) * (HH / 4);
    const int* mrow = mask + b * TT + t_base;

    float acc     = 0.0f;  // per-lane weighted partial-dot accumulator
    float pen_sum = 0.0f;  // scalar penalty-weight sum (identical across lanes)

    #pragma unroll 8
    for (int i = 0; i < ROWS_PER_WARP; i++) {
        const float4* xr = xbase + (size_t)i * (HH / 4);
        float4 a  = __ldcs(xr + lane);
        float4 c2 = __ldcs(xr + 32 + lane);

        const int t = t_base + i;
        // EMA weight: alpha*(1-a)^(T-1-t) for t>0, (1-a)^(T-1) for t==0
        float wt = exp2f((float)(TT - 1 - t) * LOG2_09);
        if (t > 0) wt *= ALPHA;
        const float c = fmaf(we, wt, wm_over_T);

        float pd = a.x * wa.x;
        pd = fmaf(a.y,  wa.y, pd);
        pd = fmaf(a.z,  wa.z, pd);
        pd = fmaf(a.w,  wa.w, pd);
        pd = fmaf(c2.x, wb.x, pd);
        pd = fmaf(c2.y, wb.y, pd);
        pd = fmaf(c2.z, wb.z, pd);
        pd = fmaf(c2.w, wb.w, pd);

        acc = fmaf(c, pd, acc);
        if (__ldg(mrow + i) == 0) pen_sum += c;
    }

    // Single butterfly per warp (fixed order -> deterministic)
    #pragma unroll
    for (int off = 16; off > 0; off >>= 1)
        acc += __shfl_xor_sync(0xffffffffu, acc, off);

    const float warp_total = acc - pen_sum * (MASK_PENALTY * wsum);
    if (lane == 0) s_warp_acc[wid] = warp_total;
    __syncthreads();

    if (tid == 0) {
        float v = 0.0f;
        #pragma unroll
        for (int w = 0; w < NWARPS; w++) v += s_warp_acc[w];  // fixed order
        g_partial[blockIdx.x] = v;
        __threadfence();
        unsigned ticket = atomicAdd(&g_count, 1u);
        s_is_last = (ticket == (unsigned)(GRID - 1));
    }
    __syncthreads();

    // Last block folds all partials: warp w handles batches 4w..4w+3,
    // lane = chunk index (CHUNKS == 32). Fixed-order butterfly -> deterministic.
    if (s_is_last) {
        const float bv = __ldg(bias);
        #pragma unroll
        for (int k = 0; k < BB / NWARPS; k++) {
            const int bb = wid * (BB / NWARPS) + k;
            float v = __ldcg(&g_partial[bb * CHUNKS + lane]);
            #pragma unroll
            for (int off = 16; off > 0; off >>= 1)
                v += __shfl_xor_sync(0xffffffffu, v, off);
            if (lane == 0) out[bb] = v + bv;
        }
        if (tid == 0) g_count = 0;   // self-reset for next graph replay
    }
}

extern "C" void kernel_launch(void* const* d_in, const int* in_sizes, int n_in,
                              void* d_out, int out_size)
{
    const float* x    = (const float*)d_in[0];
    const int*   mask = (const int*)d_in[1];
    const float* we   = (const float*)d_in[2];
    const float* wm   = (const float*)d_in[3];
    const float* W    = (const float*)d_in[4];
    const float* bias = (const float*)d_in[5];
    float* out = (float*)d_out;

    pool_fused<<<GRID, NTHREADS>>>(x, mask, we, wm, W, bias, out);
}